// round 3
// baseline (speedup 1.0000x reference)
#include <cuda_runtime.h>
#include <cstdint>

#define ND 4096
#define BM 128
#define BN 128
#define BK 32
#define STAGES 4
#define KITERS (ND / BK)

#define STAGE_BYTES ((BM + BN) * BK * 4)          // 32 KB
#define TILE_OFF 0
#define SMEM_TOTAL (STAGES * STAGE_BYTES)

// Scratch (device globals are the sanctioned scratch; no cudaMalloc).
__device__ __align__(1024) float g_C [(size_t)ND * ND];
__device__ __align__(1024) float g_Xr[(size_t)ND * ND];
__device__ __align__(1024) float g_Yt[(size_t)ND * ND];

// ---------------------------------------------------------------- helpers
__device__ __forceinline__ uint32_t smem_u32(const void* p) {
    uint32_t a;
    asm("{ .reg .u64 t; cvta.to.shared.u64 t, %1; cvt.u32.u64 %0, t; }"
        : "=r"(a) : "l"(p));
    return a;
}
__device__ __forceinline__ float tf32_rna(float x) {
    uint32_t b;
    asm("cvt.rna.tf32.f32 %0, %1;" : "=r"(b) : "f"(x));
    return __uint_as_float(b);
}
__device__ __forceinline__ uint32_t swz(uint32_t off) {
    return off ^ ((off >> 3) & 0x70);  // SW128 (Swizzle<3,4,3>), 128B rows
}
__device__ __forceinline__ void cp16(uint32_t sdst, const float* gsrc) {
    asm volatile("cp.async.cg.shared.global [%0], [%1], 16;"
                 :: "r"(sdst), "l"(__cvta_generic_to_global(gsrc)) : "memory");
}
__device__ __forceinline__ void cp_commit() {
    asm volatile("cp.async.commit_group;" ::: "memory");
}
template <int N>
__device__ __forceinline__ void cp_wait() {
    asm volatile("cp.async.wait_group %0;" :: "n"(N) : "memory");
}
__device__ __forceinline__ void ldsm4(uint32_t* r, uint32_t a) {
    asm volatile("ldmatrix.sync.aligned.m8n8.x4.shared.b16 {%0,%1,%2,%3}, [%4];"
                 : "=r"(r[0]), "=r"(r[1]), "=r"(r[2]), "=r"(r[3]) : "r"(a));
}
__device__ __forceinline__ void mma1688(float* d, const uint32_t* a, const uint32_t* b) {
    asm volatile(
        "mma.sync.aligned.m16n8k8.row.col.f32.tf32.tf32.f32 "
        "{%0,%1,%2,%3}, {%4,%5,%6,%7}, {%8,%9}, {%0,%1,%2,%3};"
        : "+f"(d[0]), "+f"(d[1]), "+f"(d[2]), "+f"(d[3])
        : "r"(a[0]), "r"(a[1]), "r"(a[2]), "r"(a[3]), "r"(b[0]), "r"(b[1]));
}

// ---------------------------------------------------------------- C matrix
// C[u][i] = cos(pi*(2i+1)*u / 8192): exact integer phase mod 16384, then
// cospif with an exactly-representable fp32 argument, rounded to tf32-RN.
__global__ void gen_c_kernel(float4* __restrict__ C4) {
    int u  = blockIdx.y;
    int q  = blockIdx.x * blockDim.x + threadIdx.x;
    int i0 = q << 2;
    int base = (2 * i0 + 1) * u;
    int step = 2 * u;
    const float s = 1.0f / 8192.0f;
    float4 r;
    r.x = tf32_rna(cospif((float)((base           ) & 16383) * s));
    r.y = tf32_rna(cospif((float)((base +     step) & 16383) * s));
    r.z = tf32_rna(cospif((float)((base + 2 * step) & 16383) * s));
    r.w = tf32_rna(cospif((float)((base + 3 * step) & 16383) * s));
    C4[(size_t)u * (ND / 4) + q] = r;
}

__global__ void round_x_kernel(const float4* __restrict__ in, float4* __restrict__ out) {
    const int n4 = ND * ND / 4;
    for (int i = blockIdx.x * blockDim.x + threadIdx.x; i < n4;
         i += gridDim.x * blockDim.x) {
        float4 v = in[i];
        v.x = tf32_rna(v.x); v.y = tf32_rna(v.y);
        v.z = tf32_rna(v.z); v.w = tf32_rna(v.w);
        out[i] = v;
    }
}

// ---------------------------------------------------------------- GEMM
// D[m,n] = sum_k A[m,k]*B[n,k]  (tf32 via mma.sync, fp32 accum in registers)
// Stored TRANSPOSED through an SMEM transpose: outT[n][m] = D[m][n].
__global__ void __launch_bounds__(256, 1) dct_gemm_kernel(
    const float* __restrict__ A, const float* __restrict__ B,
    float* __restrict__ outT, int round_out)
{
    extern __shared__ __align__(1024) char smem[];
    uint32_t sb = smem_u32(smem);
    int tid = threadIdx.x;
    int wid = tid >> 5, lane = tid & 31;
    int mb = blockIdx.x, nb = blockIdx.y;

    // Per-thread cp.async slots: stage has 128 rows x 8 chunks(16B) per tile.
    // Thread handles rows (tid>>3) + 32*t, chunk (tid&7), t = 0..3, per tile.
    int crow = tid >> 3, cch = tid & 7;
    const float* Ag = A + (size_t)(mb * BM + crow) * ND + cch * 4;
    const float* Bg = B + (size_t)(nb * BN + crow) * ND + cch * 4;
    uint32_t sA = swz((uint32_t)(crow * 128 + cch * 16));

    auto issue_stage = [&](int k, int s) {
        uint32_t Ab = sb + TILE_OFF + s * STAGE_BYTES;
        uint32_t Bb = Ab + BM * 128;
        const float* ga = Ag + k * BK;
        const float* gb = Bg + k * BK;
        #pragma unroll
        for (int t = 0; t < 4; t++) {
            uint32_t so = (sA + t * 32 * 128);
            cp16(Ab + so, ga + (size_t)(t * 32) * ND);
            cp16(Bb + so, gb + (size_t)(t * 32) * ND);
        }
    };

    // prologue: stages 0..S-2
    #pragma unroll
    for (int s = 0; s < STAGES - 1; s++) {
        issue_stage(s, s);
        cp_commit();
    }

    // warp grid: 4 (m) x 2 (n); warp tile 32 x 64
    int WM = (wid >> 1) * 32;
    int WN = (wid & 1) * 64;

    float d[2][8][4];
    #pragma unroll
    for (int mt = 0; mt < 2; mt++)
        #pragma unroll
        for (int nt = 0; nt < 8; nt++)
            #pragma unroll
            for (int j = 0; j < 4; j++) d[mt][nt][j] = 0.0f;

    // ldmatrix per-lane address components (byte offsets within tile)
    uint32_t aoff = (uint32_t)((lane & 15) * 128 + (lane >> 4) * 16);
    uint32_t boff = (uint32_t)(((lane & 7) + ((lane >> 4) << 3)) * 128
                               + ((lane >> 3) & 1) * 16);

    for (int k = 0; k < KITERS; k++) {
        int s = k & (STAGES - 1);
        __syncthreads();                       // all warps done reading stage (k-1)%S
        if (k + STAGES - 1 < KITERS)
            issue_stage(k + STAGES - 1, (k + STAGES - 1) & (STAGES - 1));
        cp_commit();                           // empty commits at tail keep count uniform
        cp_wait<STAGES - 2>();                 // stage k data arrived (this thread)
        __syncthreads();                       // ... and visible to all threads

        uint32_t Ab = sb + TILE_OFF + s * STAGE_BYTES;
        uint32_t Bb = Ab + BM * 128;

        #pragma unroll
        for (int ks = 0; ks < 4; ks++) {
            uint32_t a0[4], a1[4], bfr[4][4];
            ldsm4(a0, Ab + swz((uint32_t)(WM * 128)        + aoff + ks * 32));
            ldsm4(a1, Ab + swz((uint32_t)((WM + 16) * 128) + aoff + ks * 32));
            #pragma unroll
            for (int p = 0; p < 4; p++)
                ldsm4(bfr[p], Bb + swz((uint32_t)((WN + p * 16) * 128) + boff + ks * 32));
            #pragma unroll
            for (int nt = 0; nt < 8; nt++) {
                const uint32_t* bb = &bfr[nt >> 1][(nt & 1) * 2];
                mma1688(d[0][nt], a0, bb);
                mma1688(d[1][nt], a1, bb);
            }
        }
    }

    // -------- epilogue: transpose through SMEM, coalesced float4 stores
    cp_wait<0>();
    __syncthreads();
    float* T = (float*)smem;  // [128][132]
    int g = lane >> 2, tig = lane & 3;
    #pragma unroll
    for (int mt = 0; mt < 2; mt++) {
        #pragma unroll
        for (int nt = 0; nt < 8; nt++) {
            int m = WM + mt * 16 + g;
            int n = WN + nt * 8 + 2 * tig;
            float v0 = d[mt][nt][0], v1 = d[mt][nt][1];
            float v2 = d[mt][nt][2], v3 = d[mt][nt][3];
            if (round_out) {
                v0 = tf32_rna(v0); v1 = tf32_rna(v1);
                v2 = tf32_rna(v2); v3 = tf32_rna(v3);
            }
            T[n * 132 + m]           = v0;
            T[(n + 1) * 132 + m]     = v1;
            T[n * 132 + m + 8]       = v2;
            T[(n + 1) * 132 + m + 8] = v3;
        }
    }
    __syncthreads();
    #pragma unroll
    for (int it = 0; it < 16; it++) {
        int i = tid + it * 256;
        int r = i >> 5, c = (i & 31) * 4;
        float4 v = *(float4*)&T[r * 132 + c];
        *(float4*)&outT[(size_t)(nb * BN + r) * ND + mb * BM + c] = v;
    }
}

// ---------------------------------------------------------------- host
extern "C" void kernel_launch(void* const* d_in, const int* in_sizes, int n_in,
                              void* d_out, int out_size) {
    void *pC, *pXr, *pYt;
    cudaGetSymbolAddress(&pC,  g_C);
    cudaGetSymbolAddress(&pXr, g_Xr);
    cudaGetSymbolAddress(&pYt, g_Yt);

    gen_c_kernel<<<dim3(4, ND), 256>>>((float4*)pC);
    round_x_kernel<<<2048, 256>>>((const float4*)d_in[0], (float4*)pXr);

    cudaFuncSetAttribute(dct_gemm_kernel,
                         cudaFuncAttributeMaxDynamicSharedMemorySize, SMEM_TOTAL);

    // Pass A: Y[i,v] = sum_j Xr[i,j] * C[v,j]; transposed store -> Yt[v][i]
    dct_gemm_kernel<<<dim3(ND / BM, ND / BN), 256, SMEM_TOTAL>>>(
        (const float*)pXr, (const float*)pC, (float*)pYt, 1);
    // Pass B: D[v,u] = sum_i Yt[v,i] * C[u,i]; transposed store -> out[u][v]
    dct_gemm_kernel<<<dim3(ND / BM, ND / BN), 256, SMEM_TOTAL>>>(
        (const float*)pYt, (const float*)pC, (float*)d_out, 0);
}

// round 4
// speedup vs baseline: 1.9929x; 1.9929x over previous
#include <cuda_runtime.h>
#include <cstdint>

#define ND 4096
#define KD 2048                 // folded K
#define BM 128
#define BN 128
#define BK 32
#define STAGES 4
#define KITERS (KD / BK)        // 64

#define STAGE_BYTES ((BM + BN) * BK * 4)          // 32 KB
#define SMEM_TOTAL (STAGES * STAGE_BYTES)         // 128 KB

// Scratch (device globals are the sanctioned scratch; no cudaMalloc).
__device__ __align__(1024) float g_Ce[(size_t)KD * KD];   // C[2v][j],   16MB
__device__ __align__(1024) float g_Co[(size_t)KD * KD];   // C[2v+1][j], 16MB
__device__ __align__(1024) float g_Xs[(size_t)ND * KD];   // x fold sum
__device__ __align__(1024) float g_Xa[(size_t)ND * KD];   // x fold diff
__device__ __align__(1024) float g_Yt[(size_t)ND * ND];   // pass-A result (transposed)
__device__ __align__(1024) float g_Ys[(size_t)ND * KD];
__device__ __align__(1024) float g_Ya[(size_t)ND * KD];

// ---------------------------------------------------------------- helpers
__device__ __forceinline__ uint32_t smem_u32(const void* p) {
    uint32_t a;
    asm("{ .reg .u64 t; cvta.to.shared.u64 t, %1; cvt.u32.u64 %0, t; }"
        : "=r"(a) : "l"(p));
    return a;
}
__device__ __forceinline__ float tf32_rna(float x) {
    uint32_t b;
    asm("cvt.rna.tf32.f32 %0, %1;" : "=r"(b) : "f"(x));
    return __uint_as_float(b);
}
__device__ __forceinline__ uint32_t swz(uint32_t off) {
    return off ^ ((off >> 3) & 0x70);  // SW128 (Swizzle<3,4,3>), 128B rows
}
__device__ __forceinline__ void cp16(uint32_t sdst, const float* gsrc) {
    asm volatile("cp.async.cg.shared.global [%0], [%1], 16;"
                 :: "r"(sdst), "l"(__cvta_generic_to_global(gsrc)) : "memory");
}
__device__ __forceinline__ void cp_commit() {
    asm volatile("cp.async.commit_group;" ::: "memory");
}
template <int N>
__device__ __forceinline__ void cp_wait() {
    asm volatile("cp.async.wait_group %0;" :: "n"(N) : "memory");
}
__device__ __forceinline__ void ldsm4(uint32_t* r, uint32_t a) {
    asm volatile("ldmatrix.sync.aligned.m8n8.x4.shared.b16 {%0,%1,%2,%3}, [%4];"
                 : "=r"(r[0]), "=r"(r[1]), "=r"(r[2]), "=r"(r[3]) : "r"(a));
}
__device__ __forceinline__ void mma1688(float* d, const uint32_t* a, const uint32_t* b) {
    asm volatile(
        "mma.sync.aligned.m16n8k8.row.col.f32.tf32.tf32.f32 "
        "{%0,%1,%2,%3}, {%4,%5,%6,%7}, {%8,%9}, {%0,%1,%2,%3};"
        : "+f"(d[0]), "+f"(d[1]), "+f"(d[2]), "+f"(d[3])
        : "r"(a[0]), "r"(a[1]), "r"(a[2]), "r"(a[3]), "r"(b[0]), "r"(b[1]));
}

// ---------------------------------------------------------------- basis
// Ce[v][j] = cos(pi*(2j+1)*(2v)/8192), Co[v][j] = cos(pi*(2j+1)*(2v+1)/8192)
// Exact integer phase mod 16384, cospif on exact fp32 argument, tf32-RN.
__global__ void gen_c_kernel(float4* __restrict__ Ce4, float4* __restrict__ Co4) {
    int v  = blockIdx.y;                              // 0..2047
    int q  = blockIdx.x * blockDim.x + threadIdx.x;   // 0..511
    int j0 = q << 2;
    const float s = 1.0f / 8192.0f;
    int ke = 2 * v, ko = 2 * v + 1;
    int be = (2 * j0 + 1) * ke, se = 2 * ke;
    int bo = (2 * j0 + 1) * ko, so = 2 * ko;
    float4 re, ro;
    re.x = tf32_rna(cospif((float)((be         ) & 16383) * s));
    re.y = tf32_rna(cospif((float)((be +     se) & 16383) * s));
    re.z = tf32_rna(cospif((float)((be + 2 * se) & 16383) * s));
    re.w = tf32_rna(cospif((float)((be + 3 * se) & 16383) * s));
    ro.x = tf32_rna(cospif((float)((bo         ) & 16383) * s));
    ro.y = tf32_rna(cospif((float)((bo +     so) & 16383) * s));
    ro.z = tf32_rna(cospif((float)((bo + 2 * so) & 16383) * s));
    ro.w = tf32_rna(cospif((float)((bo + 3 * so) & 16383) * s));
    Ce4[(size_t)v * (KD / 4) + q] = re;
    Co4[(size_t)v * (KD / 4) + q] = ro;
}

// Fold rows of length ND into sum/diff halves of length KD, tf32-rounded.
__global__ void fold_kernel(const float* __restrict__ src,
                            float* __restrict__ s_out, float* __restrict__ a_out) {
    const int qpr = KD / 4;                     // float4 per output row
    const size_t total = (size_t)ND * qpr;
    for (size_t idx = blockIdx.x * blockDim.x + threadIdx.x; idx < total;
         idx += (size_t)gridDim.x * blockDim.x) {
        size_t row = idx / qpr;
        int q = (int)(idx % qpr);
        const float* rp = src + row * ND;
        float4 f  = *(const float4*)&rp[q * 4];
        float4 rv = *(const float4*)&rp[ND - 4 - q * 4];   // mirrored quad
        float4 sv, av;
        sv.x = tf32_rna(f.x + rv.w);  av.x = tf32_rna(f.x - rv.w);
        sv.y = tf32_rna(f.y + rv.z);  av.y = tf32_rna(f.y - rv.z);
        sv.z = tf32_rna(f.z + rv.y);  av.z = tf32_rna(f.z - rv.y);
        sv.w = tf32_rna(f.w + rv.x);  av.w = tf32_rna(f.w - rv.x);
        *(float4*)&s_out[row * KD + q * 4] = sv;
        *(float4*)&a_out[row * KD + q * 4] = av;
    }
}

// ---------------------------------------------------------------- GEMM
// D[m,n] = sum_k A[m,k]*B[n,k], K = KD.  nb<16 -> (Ae,Be) even parity,
// nb>=16 -> (Ao,Bo) odd parity. Transposed store: outT[2*n+par][m].
__global__ void __launch_bounds__(256, 1) dct_gemm_kernel(
    const float* __restrict__ Ae, const float* __restrict__ Ao,
    const float* __restrict__ Be, const float* __restrict__ Bo,
    float* __restrict__ outT)
{
    extern __shared__ __align__(1024) char smem[];
    uint32_t sb = smem_u32(smem);
    int tid = threadIdx.x;
    int wid = tid >> 5, lane = tid & 31;
    int mb = blockIdx.x;
    int nb = blockIdx.y;
    int par = nb >> 4;
    int nbe = nb & 15;
    const float* A = par ? Ao : Ae;
    const float* B = par ? Bo : Be;

    // Per-thread cp.async slots: 128 rows x 8 chunks(16B) per tile.
    int crow = tid >> 3, cch = tid & 7;
    const float* Ag = A + (size_t)(mb * BM + crow) * KD + cch * 4;
    const float* Bg = B + (size_t)(nbe * BN + crow) * KD + cch * 4;
    uint32_t sA = swz((uint32_t)(crow * 128 + cch * 16));

    auto issue_stage = [&](int k, int s) {
        uint32_t Ab = sb + s * STAGE_BYTES;
        uint32_t Bb = Ab + BM * 128;
        const float* ga = Ag + k * BK;
        const float* gb = Bg + k * BK;
        #pragma unroll
        for (int t = 0; t < 4; t++) {
            uint32_t so = sA + t * 32 * 128;
            cp16(Ab + so, ga + (size_t)(t * 32) * KD);
            cp16(Bb + so, gb + (size_t)(t * 32) * KD);
        }
    };

    #pragma unroll
    for (int s = 0; s < STAGES - 1; s++) {
        issue_stage(s, s);
        cp_commit();
    }

    // warp grid: 4 (m) x 2 (n); warp tile 32 x 64
    int WM = (wid >> 1) * 32;
    int WN = (wid & 1) * 64;

    float d[2][8][4];
    #pragma unroll
    for (int mt = 0; mt < 2; mt++)
        #pragma unroll
        for (int nt = 0; nt < 8; nt++)
            #pragma unroll
            for (int j = 0; j < 4; j++) d[mt][nt][j] = 0.0f;

    uint32_t aoff = (uint32_t)((lane & 15) * 128 + (lane >> 4) * 16);
    uint32_t boff = (uint32_t)(((lane & 7) + ((lane >> 4) << 3)) * 128
                               + ((lane >> 3) & 1) * 16);

    for (int k = 0; k < KITERS; k++) {
        int s = k & (STAGES - 1);
        cp_wait<STAGES - 2>();       // this thread's stage-k data arrived
        __syncthreads();             // visible to all; stage k-1 fully consumed
        if (k + STAGES - 1 < KITERS)
            issue_stage(k + STAGES - 1, (k + STAGES - 1) & (STAGES - 1));
        cp_commit();                 // empty commits at tail keep count uniform

        uint32_t Ab = sb + s * STAGE_BYTES;
        uint32_t Bb = Ab + BM * 128;

        #pragma unroll
        for (int ks = 0; ks < 4; ks++) {
            uint32_t a0[4], a1[4], bfr[4][4];
            ldsm4(a0, Ab + swz((uint32_t)(WM * 128)        + aoff + ks * 32));
            ldsm4(a1, Ab + swz((uint32_t)((WM + 16) * 128) + aoff + ks * 32));
            #pragma unroll
            for (int p = 0; p < 4; p++)
                ldsm4(bfr[p], Bb + swz((uint32_t)((WN + p * 16) * 128) + boff + ks * 32));
            #pragma unroll
            for (int nt = 0; nt < 8; nt++) {
                const uint32_t* bb = &bfr[nt >> 1][(nt & 1) * 2];
                mma1688(d[0][nt], a0, bb);
                mma1688(d[1][nt], a1, bb);
            }
        }
    }

    // -------- epilogue: transpose through SMEM, coalesced float4 stores
    cp_wait<0>();
    __syncthreads();
    float* T = (float*)smem;  // [128][132]
    int g = lane >> 2, tig = lane & 3;
    #pragma unroll
    for (int mt = 0; mt < 2; mt++) {
        #pragma unroll
        for (int nt = 0; nt < 8; nt++) {
            int m = WM + mt * 16 + g;
            int n = WN + nt * 8 + 2 * tig;
            T[n * 132 + m]           = d[mt][nt][0];
            T[(n + 1) * 132 + m]     = d[mt][nt][1];
            T[n * 132 + m + 8]       = d[mt][nt][2];
            T[(n + 1) * 132 + m + 8] = d[mt][nt][3];
        }
    }
    __syncthreads();
    #pragma unroll
    for (int it = 0; it < 16; it++) {
        int i = tid + it * 256;
        int r = i >> 5, c = (i & 31) * 4;
        float4 v = *(float4*)&T[r * 132 + c];
        size_t orow = (size_t)(2 * (nbe * BN + r) + par);
        *(float4*)&outT[orow * ND + mb * BM + c] = v;
    }
}

// ---------------------------------------------------------------- host
extern "C" void kernel_launch(void* const* d_in, const int* in_sizes, int n_in,
                              void* d_out, int out_size) {
    void *pCe, *pCo, *pXs, *pXa, *pYt, *pYs, *pYa;
    cudaGetSymbolAddress(&pCe, g_Ce);
    cudaGetSymbolAddress(&pCo, g_Co);
    cudaGetSymbolAddress(&pXs, g_Xs);
    cudaGetSymbolAddress(&pXa, g_Xa);
    cudaGetSymbolAddress(&pYt, g_Yt);
    cudaGetSymbolAddress(&pYs, g_Ys);
    cudaGetSymbolAddress(&pYa, g_Ya);

    gen_c_kernel<<<dim3(2, KD), 256>>>((float4*)pCe, (float4*)pCo);
    fold_kernel<<<2048, 256>>>((const float*)d_in[0], (float*)pXs, (float*)pXa);

    cudaFuncSetAttribute(dct_gemm_kernel,
                         cudaFuncAttributeMaxDynamicSharedMemorySize, SMEM_TOTAL);

    // Pass A: Y[i,v]; even v from (Xs,Ce), odd v from (Xa,Co) -> Yt[v][i]
    dct_gemm_kernel<<<dim3(ND / BM, 2 * KD / BN), 256, SMEM_TOTAL>>>(
        (const float*)pXs, (const float*)pXa,
        (const float*)pCe, (const float*)pCo, (float*)pYt);

    // Fold Yt along i for pass B
    fold_kernel<<<2048, 256>>>((const float*)pYt, (float*)pYs, (float*)pYa);

    // Pass B: out[u][v]; even u from (Ys,Ce), odd u from (Ya,Co)
    dct_gemm_kernel<<<dim3(ND / BM, 2 * KD / BN), 256, SMEM_TOTAL>>>(
        (const float*)pYs, (const float*)pYa,
        (const float*)pCe, (const float*)pCo, (float*)d_out);
}

// round 5
// speedup vs baseline: 2.3842x; 1.1963x over previous
#include <cuda_runtime.h>
#include <cstdint>

#define ND 4096
#define KD 2048                 // folded K
#define BM 128
#define BN 128
#define BK 32
#define STAGES 3
#define KITERS (KD / BK)        // 64

#define STAGE_BYTES ((BM + BN) * BK * 4)          // 32 KB
#define SMEM_TOTAL (STAGES * STAGE_BYTES)         // 96 KB -> 2 CTAs/SM

// Scratch (device globals are the sanctioned scratch; no cudaMalloc).
__device__ __align__(1024) float g_Ce[(size_t)KD * KD];   // C[2v][j]
__device__ __align__(1024) float g_Co[(size_t)KD * KD];   // C[2v+1][j]
__device__ __align__(1024) float g_Xs[(size_t)ND * KD];
__device__ __align__(1024) float g_Xa[(size_t)ND * KD];
__device__ __align__(1024) float g_Yt[(size_t)ND * ND];
__device__ __align__(1024) float g_Ys[(size_t)ND * KD];
__device__ __align__(1024) float g_Ya[(size_t)ND * KD];

// ---------------------------------------------------------------- helpers
__device__ __forceinline__ uint32_t smem_u32(const void* p) {
    uint32_t a;
    asm("{ .reg .u64 t; cvta.to.shared.u64 t, %1; cvt.u32.u64 %0, t; }"
        : "=r"(a) : "l"(p));
    return a;
}
__device__ __forceinline__ float tf32_rna(float x) {
    uint32_t b;
    asm("cvt.rna.tf32.f32 %0, %1;" : "=r"(b) : "f"(x));
    return __uint_as_float(b);
}
__device__ __forceinline__ uint32_t swz(uint32_t off) {
    return off ^ ((off >> 3) & 0x70);  // SW128 (Swizzle<3,4,3>), 128B rows
}
__device__ __forceinline__ void cp16(uint32_t sdst, const float* gsrc) {
    asm volatile("cp.async.cg.shared.global [%0], [%1], 16;"
                 :: "r"(sdst), "l"(__cvta_generic_to_global(gsrc)) : "memory");
}
__device__ __forceinline__ void cp_commit() {
    asm volatile("cp.async.commit_group;" ::: "memory");
}
template <int N>
__device__ __forceinline__ void cp_wait() {
    asm volatile("cp.async.wait_group %0;" :: "n"(N) : "memory");
}
__device__ __forceinline__ void ldsm4(uint32_t* r, uint32_t a) {
    asm volatile("ldmatrix.sync.aligned.m8n8.x4.shared.b16 {%0,%1,%2,%3}, [%4];"
                 : "=r"(r[0]), "=r"(r[1]), "=r"(r[2]), "=r"(r[3]) : "r"(a));
}
__device__ __forceinline__ void mma1688(float* d, const uint32_t* a, const uint32_t* b) {
    asm volatile(
        "mma.sync.aligned.m16n8k8.row.col.f32.tf32.tf32.f32 "
        "{%0,%1,%2,%3}, {%4,%5,%6,%7}, {%8,%9}, {%0,%1,%2,%3};"
        : "+f"(d[0]), "+f"(d[1]), "+f"(d[2]), "+f"(d[3])
        : "r"(a[0]), "r"(a[1]), "r"(a[2]), "r"(a[3]), "r"(b[0]), "r"(b[1]));
}

// ---------------------------------------------------------------- basis
__global__ void gen_c_kernel(float4* __restrict__ Ce4, float4* __restrict__ Co4) {
    int v  = blockIdx.y;
    int q  = blockIdx.x * blockDim.x + threadIdx.x;
    int j0 = q << 2;
    const float s = 1.0f / 8192.0f;
    int ke = 2 * v, ko = 2 * v + 1;
    int be = (2 * j0 + 1) * ke, se = 2 * ke;
    int bo = (2 * j0 + 1) * ko, so = 2 * ko;
    float4 re, ro;
    re.x = tf32_rna(cospif((float)((be         ) & 16383) * s));
    re.y = tf32_rna(cospif((float)((be +     se) & 16383) * s));
    re.z = tf32_rna(cospif((float)((be + 2 * se) & 16383) * s));
    re.w = tf32_rna(cospif((float)((be + 3 * se) & 16383) * s));
    ro.x = tf32_rna(cospif((float)((bo         ) & 16383) * s));
    ro.y = tf32_rna(cospif((float)((bo +     so) & 16383) * s));
    ro.z = tf32_rna(cospif((float)((bo + 2 * so) & 16383) * s));
    ro.w = tf32_rna(cospif((float)((bo + 3 * so) & 16383) * s));
    Ce4[(size_t)v * (KD / 4) + q] = re;
    Co4[(size_t)v * (KD / 4) + q] = ro;
}

// Fold rows of length ND into sum/diff halves of length KD, tf32-rounded.
__global__ void fold_kernel(const float* __restrict__ src,
                            float* __restrict__ s_out, float* __restrict__ a_out) {
    const int qpr = KD / 4;
    const size_t total = (size_t)ND * qpr;
    for (size_t idx = blockIdx.x * blockDim.x + threadIdx.x; idx < total;
         idx += (size_t)gridDim.x * blockDim.x) {
        size_t row = idx / qpr;
        int q = (int)(idx % qpr);
        const float* rp = src + row * ND;
        float4 f  = *(const float4*)&rp[q * 4];
        float4 rv = *(const float4*)&rp[ND - 4 - q * 4];
        float4 sv, av;
        sv.x = tf32_rna(f.x + rv.w);  av.x = tf32_rna(f.x - rv.w);
        sv.y = tf32_rna(f.y + rv.z);  av.y = tf32_rna(f.y - rv.z);
        sv.z = tf32_rna(f.z + rv.y);  av.z = tf32_rna(f.z - rv.y);
        sv.w = tf32_rna(f.w + rv.x);  av.w = tf32_rna(f.w - rv.x);
        *(float4*)&s_out[row * KD + q * 4] = sv;
        *(float4*)&a_out[row * KD + q * 4] = av;
    }
}

// ---------------------------------------------------------------- GEMM
// D[m,n] = sum_k A[m,k]*B[n,k], K = KD.  nb<16 -> even parity, else odd.
// Transposed store: outT[2*n+par][m].
__global__ void __launch_bounds__(256, 2) dct_gemm_kernel(
    const float* __restrict__ Ae, const float* __restrict__ Ao,
    const float* __restrict__ Be, const float* __restrict__ Bo,
    float* __restrict__ outT)
{
    extern __shared__ __align__(1024) char smem[];
    uint32_t sb = smem_u32(smem);
    int tid = threadIdx.x;
    int wid = tid >> 5, lane = tid & 31;
    int mb = blockIdx.x;
    int nb = blockIdx.y;
    int par = nb >> 4;
    int nbe = nb & 15;
    const float* A = par ? Ao : Ae;
    const float* B = par ? Bo : Be;

    int crow = tid >> 3, cch = tid & 7;
    const float* Ag = A + (size_t)(mb * BM + crow) * KD + cch * 4;
    const float* Bg = B + (size_t)(nbe * BN + crow) * KD + cch * 4;
    uint32_t sA = swz((uint32_t)(crow * 128 + cch * 16));

    auto issue_stage = [&](int k, int s) {
        uint32_t Ab = sb + s * STAGE_BYTES;
        uint32_t Bb = Ab + BM * 128;
        const float* ga = Ag + k * BK;
        const float* gb = Bg + k * BK;
        #pragma unroll
        for (int t = 0; t < 4; t++) {
            uint32_t so = sA + t * 32 * 128;
            cp16(Ab + so, ga + (size_t)(t * 32) * KD);
            cp16(Bb + so, gb + (size_t)(t * 32) * KD);
        }
    };

    #pragma unroll
    for (int s = 0; s < STAGES - 1; s++) {
        issue_stage(s, s);
        cp_commit();
    }

    // warp grid: 4 (m) x 2 (n); warp tile 32 x 64
    int WM = (wid >> 1) * 32;
    int WN = (wid & 1) * 64;

    float d[2][8][4];
    #pragma unroll
    for (int mt = 0; mt < 2; mt++)
        #pragma unroll
        for (int nt = 0; nt < 8; nt++)
            #pragma unroll
            for (int j = 0; j < 4; j++) d[mt][nt][j] = 0.0f;

    uint32_t aoff = (uint32_t)((lane & 15) * 128 + (lane >> 4) * 16);
    uint32_t boff = (uint32_t)(((lane & 7) + ((lane >> 4) << 3)) * 128
                               + ((lane >> 3) & 1) * 16);

    int s = 0;
    for (int k = 0; k < KITERS; k++) {
        cp_wait<STAGES - 2>();       // stage-k data arrived (this thread)
        __syncthreads();             // visible to all; stage k-1 fully consumed
        if (k + STAGES - 1 < KITERS)
            issue_stage(k + STAGES - 1, (k + STAGES - 1) % STAGES);
        cp_commit();                 // empty commits at tail keep count uniform

        uint32_t Ab = sb + s * STAGE_BYTES;
        uint32_t Bb = Ab + BM * 128;

        #pragma unroll
        for (int ks = 0; ks < 4; ks++) {
            uint32_t a0[4], a1[4], bfr[2][4];
            ldsm4(a0, Ab + swz((uint32_t)(WM * 128)        + aoff + ks * 32));
            ldsm4(a1, Ab + swz((uint32_t)((WM + 16) * 128) + aoff + ks * 32));
            // first half: n-cols [WN, WN+32)
            ldsm4(bfr[0], Bb + swz((uint32_t)(WN * 128)        + boff + ks * 32));
            ldsm4(bfr[1], Bb + swz((uint32_t)((WN + 16) * 128) + boff + ks * 32));
            #pragma unroll
            for (int nt = 0; nt < 4; nt++) {
                const uint32_t* bb = &bfr[nt >> 1][(nt & 1) * 2];
                mma1688(d[0][nt], a0, bb);
                mma1688(d[1][nt], a1, bb);
            }
            // second half: n-cols [WN+32, WN+64)
            ldsm4(bfr[0], Bb + swz((uint32_t)((WN + 32) * 128) + boff + ks * 32));
            ldsm4(bfr[1], Bb + swz((uint32_t)((WN + 48) * 128) + boff + ks * 32));
            #pragma unroll
            for (int nt = 0; nt < 4; nt++) {
                const uint32_t* bb = &bfr[nt >> 1][(nt & 1) * 2];
                mma1688(d[0][nt + 4], a0, bb);
                mma1688(d[1][nt + 4], a1, bb);
            }
        }
        s = (s == STAGES - 1) ? 0 : s + 1;
    }

    // -------- epilogue: transpose through SMEM, coalesced float4 stores
    cp_wait<0>();
    __syncthreads();
    float* T = (float*)smem;  // [128][132] = 67.6KB <= 96KB
    int g = lane >> 2, tig = lane & 3;
    #pragma unroll
    for (int mt = 0; mt < 2; mt++) {
        #pragma unroll
        for (int nt = 0; nt < 8; nt++) {
            int m = WM + mt * 16 + g;
            int n = WN + nt * 8 + 2 * tig;
            T[n * 132 + m]           = d[mt][nt][0];
            T[(n + 1) * 132 + m]     = d[mt][nt][1];
            T[n * 132 + m + 8]       = d[mt][nt][2];
            T[(n + 1) * 132 + m + 8] = d[mt][nt][3];
        }
    }
    __syncthreads();
    #pragma unroll
    for (int it = 0; it < 16; it++) {
        int i = tid + it * 256;
        int r = i >> 5, c = (i & 31) * 4;
        float4 v = *(float4*)&T[r * 132 + c];
        size_t orow = (size_t)(2 * (nbe * BN + r) + par);
        *(float4*)&outT[orow * ND + mb * BM + c] = v;
    }
}

// ---------------------------------------------------------------- host
extern "C" void kernel_launch(void* const* d_in, const int* in_sizes, int n_in,
                              void* d_out, int out_size) {
    void *pCe, *pCo, *pXs, *pXa, *pYt, *pYs, *pYa;
    cudaGetSymbolAddress(&pCe, g_Ce);
    cudaGetSymbolAddress(&pCo, g_Co);
    cudaGetSymbolAddress(&pXs, g_Xs);
    cudaGetSymbolAddress(&pXa, g_Xa);
    cudaGetSymbolAddress(&pYt, g_Yt);
    cudaGetSymbolAddress(&pYs, g_Ys);
    cudaGetSymbolAddress(&pYa, g_Ya);

    gen_c_kernel<<<dim3(2, KD), 256>>>((float4*)pCe, (float4*)pCo);
    fold_kernel<<<2048, 256>>>((const float*)d_in[0], (float*)pXs, (float*)pXa);

    cudaFuncSetAttribute(dct_gemm_kernel,
                         cudaFuncAttributeMaxDynamicSharedMemorySize, SMEM_TOTAL);

    // Pass A: Y[i,v]; even v from (Xs,Ce), odd v from (Xa,Co) -> Yt[v][i]
    dct_gemm_kernel<<<dim3(ND / BM, 2 * KD / BN), 256, SMEM_TOTAL>>>(
        (const float*)pXs, (const float*)pXa,
        (const float*)pCe, (const float*)pCo, (float*)pYt);

    // Fold Yt along i for pass B
    fold_kernel<<<2048, 256>>>((const float*)pYt, (float*)pYs, (float*)pYa);

    // Pass B: out[u][v]; even u from (Ys,Ce), odd u from (Ya,Co)
    dct_gemm_kernel<<<dim3(ND / BM, 2 * KD / BN), 256, SMEM_TOTAL>>>(
        (const float*)pYs, (const float*)pYa,
        (const float*)pCe, (const float*)pCo, (float*)d_out);
}